// round 1
// baseline (speedup 1.0000x reference)
#include <cuda_runtime.h>
#include <cstdint>
#include <cstddef>

#define LATENT   2000
#define NG       10000
#define KER      20
#define BATCH    128
#define NTILE    80          // groups per CTA; 10000 = 125 * 80 exactly
#define KTILE    16
#define NCTA     125
#define KTILES   125         // 2000 / 16
#define ZS_PITCH 136         // padded: bank = 8*(lane&3) + (lane>>2) -> conflict-free A reads
#define WS_PITCH 88          // padded: bank = 24*(lane&3) + (lane>>2) -> conflict-free B reads

__device__ __forceinline__ uint32_t f2tf32(float x) {
    uint32_t r;
    asm("cvt.rna.tf32.f32 %0, %1;" : "=r"(r) : "f"(x));
    return r;
}

__device__ __forceinline__ float lrelu_sig(float y) {
    y = (y >= 0.f) ? y : 0.1f * y;
    return __fdividef(1.f, 1.f + __expf(-y));
}

__global__ void __launch_bounds__(256, 1)
fused_decoder(const float* __restrict__ z,
              const float* __restrict__ Wfc,
              const float* __restrict__ gamma,
              const float* __restrict__ beta,
              const float* __restrict__ convw,
              const float* __restrict__ convb,
              float* __restrict__ out)
{
    __shared__ uint32_t zs[2][KTILE][ZS_PITCH];   // z tile, tf32, [k][m]
    __shared__ uint32_t ws[2][KTILE][WS_PITCH];   // W tile, tf32, [k][n]
    __shared__ float red_s[8][NTILE];
    __shared__ float red_q[8][NTILE];
    __shared__ float sscale[NTILE];
    __shared__ float sshift[NTILE];
    __shared__ __align__(16) float scw[NTILE * KER];
    __shared__ float scb[NTILE];

    const int tid  = threadIdx.x;
    const int w    = tid >> 5;      // warp id 0..7 -> m-tile (16 rows each)
    const int lane = tid & 31;
    const int g0   = blockIdx.x * NTILE;

    // conv weights/bias for this group block (contiguous copy)
    for (int i = tid; i < NTILE * KER; i += 256)
        scw[i] = convw[(size_t)g0 * KER + i];
    if (tid < NTILE) scb[tid] = convb[g0 + tid];

    // -------- GEMM staging setup --------
    const int  zrow = tid >> 2;            // 0..63
    const int  c4   = (tid & 3) * 4;       // k sub-offset within tile
    const float* zptr0 = z   + (size_t)zrow * LATENT + c4;
    const float* zptr1 = z   + (size_t)(zrow + 64) * LATENT + c4;
    const float* wptr0 = Wfc + (size_t)(g0 + zrow) * LATENT + c4;
    const bool   w2    = (tid < 64);
    const float* wptr1 = Wfc + (size_t)(g0 + 64 + (tid >> 2)) * LATENT + (tid & 3) * 4;
    const int    wrow1 = 64 + (tid >> 2);
    const int    wc41  = (tid & 3) * 4;

    float4 zr0, zr1, wr0, wr1;

    auto stage = [&](int p) {
        zs[p][c4 + 0][zrow]      = f2tf32(zr0.x);
        zs[p][c4 + 1][zrow]      = f2tf32(zr0.y);
        zs[p][c4 + 2][zrow]      = f2tf32(zr0.z);
        zs[p][c4 + 3][zrow]      = f2tf32(zr0.w);
        zs[p][c4 + 0][zrow + 64] = f2tf32(zr1.x);
        zs[p][c4 + 1][zrow + 64] = f2tf32(zr1.y);
        zs[p][c4 + 2][zrow + 64] = f2tf32(zr1.z);
        zs[p][c4 + 3][zrow + 64] = f2tf32(zr1.w);
        ws[p][c4 + 0][zrow]      = f2tf32(wr0.x);
        ws[p][c4 + 1][zrow]      = f2tf32(wr0.y);
        ws[p][c4 + 2][zrow]      = f2tf32(wr0.z);
        ws[p][c4 + 3][zrow]      = f2tf32(wr0.w);
        if (w2) {
            ws[p][wc41 + 0][wrow1] = f2tf32(wr1.x);
            ws[p][wc41 + 1][wrow1] = f2tf32(wr1.y);
            ws[p][wc41 + 2][wrow1] = f2tf32(wr1.z);
            ws[p][wc41 + 3][wrow1] = f2tf32(wr1.w);
        }
    };

    float d[10][4];
    #pragma unroll
    for (int i = 0; i < 10; ++i)
        #pragma unroll
        for (int j = 0; j < 4; ++j) d[i][j] = 0.f;

    // prologue: load + stage k-tile 0
    zr0 = *(const float4*)zptr0;
    zr1 = *(const float4*)zptr1;
    wr0 = *(const float4*)wptr0;
    if (w2) wr1 = *(const float4*)wptr1;
    stage(0);

    const int kq = lane & 3;     // k within quad
    const int rq = lane >> 2;    // row/col group id
    const int mw = w << 4;

    #pragma unroll 1
    for (int t = 0; t < KTILES; ++t) {
        __syncthreads();
        const int p = t & 1;
        if (t + 1 < KTILES) {
            const int off = (t + 1) * KTILE;
            zr0 = *(const float4*)(zptr0 + off);
            zr1 = *(const float4*)(zptr1 + off);
            wr0 = *(const float4*)(wptr0 + off);
            if (w2) wr1 = *(const float4*)(wptr1 + off);
        }
        #pragma unroll
        for (int ks = 0; ks < 2; ++ks) {
            const int kA = ks * 8 + kq;
            const uint32_t a0 = zs[p][kA][mw + rq];
            const uint32_t a1 = zs[p][kA][mw + rq + 8];
            const uint32_t a2 = zs[p][kA + 4][mw + rq];
            const uint32_t a3 = zs[p][kA + 4][mw + rq + 8];
            #pragma unroll
            for (int nt = 0; nt < 10; ++nt) {
                const uint32_t b0 = ws[p][kA][nt * 8 + rq];
                const uint32_t b1 = ws[p][kA + 4][nt * 8 + rq];
                asm volatile(
                    "mma.sync.aligned.m16n8k8.row.col.f32.tf32.tf32.f32 "
                    "{%0,%1,%2,%3}, {%4,%5,%6,%7}, {%8,%9}, {%0,%1,%2,%3};\n"
                    : "+f"(d[nt][0]), "+f"(d[nt][1]), "+f"(d[nt][2]), "+f"(d[nt][3])
                    : "r"(a0), "r"(a1), "r"(a2), "r"(a3), "r"(b0), "r"(b1));
            }
        }
        if (t + 1 < KTILES) stage((t + 1) & 1);
    }

    // -------- BatchNorm stats (b_fc cancels analytically under mean-subtract) --------
    // lane holds rows {rq, rq+8} of its warp's 16-row strip; cols nt*8 + 2*kq + {0,1}
    #pragma unroll
    for (int nt = 0; nt < 10; ++nt) {
        float s0 = d[nt][0] + d[nt][2];
        float s1 = d[nt][1] + d[nt][3];
        float q0 = d[nt][0] * d[nt][0] + d[nt][2] * d[nt][2];
        float q1 = d[nt][1] * d[nt][1] + d[nt][3] * d[nt][3];
        #pragma unroll
        for (int o = 4; o < 32; o <<= 1) {
            s0 += __shfl_xor_sync(0xffffffffu, s0, o);
            s1 += __shfl_xor_sync(0xffffffffu, s1, o);
            q0 += __shfl_xor_sync(0xffffffffu, q0, o);
            q1 += __shfl_xor_sync(0xffffffffu, q1, o);
        }
        if (rq == 0) {
            const int n = nt * 8 + kq * 2;
            red_s[w][n]     = s0;
            red_s[w][n + 1] = s1;
            red_q[w][n]     = q0;
            red_q[w][n + 1] = q1;
        }
    }
    __syncthreads();
    if (tid < NTILE) {
        float s = 0.f, qq = 0.f;
        #pragma unroll
        for (int i = 0; i < 8; ++i) { s += red_s[i][tid]; qq += red_q[i][tid]; }
        const float mean = s * (1.f / BATCH);
        const float var  = qq * (1.f / BATCH) - mean * mean;
        const float sc   = gamma[g0 + tid] * rsqrtf(var + 1e-5f);
        sscale[tid] = sc;
        sshift[tid] = beta[g0 + tid] - mean * sc;
    }
    __syncthreads();

    // -------- Epilogue: BN + LeakyReLU + outer-product conv + LeakyReLU + sigmoid --------
    #pragma unroll
    for (int nt = 0; nt < 10; ++nt) {
        #pragma unroll
        for (int c = 0; c < 4; ++c) {
            const int n = nt * 8 + kq * 2 + (c & 1);
            const int m = mw + rq + ((c >> 1) << 3);
            float hn = d[nt][c] * sscale[n] + sshift[n];
            hn = (hn >= 0.f) ? hn : 0.1f * hn;
            const float cb = scb[n];
            float* op = out + (size_t)m * ((size_t)NG * KER) + (size_t)(g0 + n) * KER;
            #pragma unroll
            for (int kc = 0; kc < 5; ++kc) {
                const float4 wv = *(const float4*)&scw[n * KER + kc * 4];
                float4 yv;
                yv.x = lrelu_sig(hn * wv.x + cb);
                yv.y = lrelu_sig(hn * wv.y + cb);
                yv.z = lrelu_sig(hn * wv.z + cb);
                yv.w = lrelu_sig(hn * wv.w + cb);
                *(float4*)(op + kc * 4) = yv;
            }
        }
    }
}

extern "C" void kernel_launch(void* const* d_in, const int* in_sizes, int n_in,
                              void* d_out, int out_size) {
    const float* z     = (const float*)d_in[0];
    const float* Wfc   = (const float*)d_in[1];
    // d_in[2] = b_fc: analytically cancelled by batch-norm mean subtraction
    const float* gamma = (const float*)d_in[3];
    const float* beta  = (const float*)d_in[4];
    const float* convw = (const float*)d_in[5];
    const float* convb = (const float*)d_in[6];
    fused_decoder<<<NCTA, 256>>>(z, Wfc, gamma, beta, convw, convb, (float*)d_out);
}

// round 2
// speedup vs baseline: 2.4987x; 2.4987x over previous
#include <cuda_runtime.h>
#include <cstdint>
#include <cstddef>

#define LATENT   2000
#define NG       10000
#define KER      20
#define BATCH    128
#define NTILE    80          // groups per CTA; 10000 = 125*80
#define KTILE    16
#define NCTA     125
#define KTILES   125         // 2000/16
#define STAGES   5
#define ZROW     20          // padded floats per row (16 data + 4 pad) -> conflict-free LDS
#define STAGE_Z  (128*ZROW)  // 2560 floats
#define STAGE_W  (80*ZROW)   // 1600 floats
#define STAGE_F  (STAGE_Z+STAGE_W)  // 4160 floats
#define SMEM_FLOATS (STAGES*STAGE_F + 640 + 640 + 80 + 80 + 1600 + 80 + 10240)
#define SMEM_BYTES  (SMEM_FLOATS*4)

__device__ __forceinline__ void cp16(uint32_t dst, const void* src) {
    asm volatile("cp.async.cg.shared.global [%0], [%1], 16;\n" :: "r"(dst), "l"(src));
}
__device__ __forceinline__ void cp_commit() {
    asm volatile("cp.async.commit_group;\n");
}

__device__ __forceinline__ float sigf(float y) {
    // y already leaky-relu'd; sigmoid via ex2+rcp (2 MUFU)
    return __fdividef(1.f, 1.f + __expf(-y));
}

__global__ void __launch_bounds__(512, 1)
fused_decoder(const float* __restrict__ z,
              const float* __restrict__ Wfc,
              const float* __restrict__ gamma,
              const float* __restrict__ beta,
              const float* __restrict__ convw,
              const float* __restrict__ convb,
              float* __restrict__ out)
{
    extern __shared__ float sm[];
    float* stg    = sm;                        // STAGES*STAGE_F
    float* red_s  = sm + STAGES*STAGE_F;       // 8*80
    float* red_q  = red_s + 640;               // 8*80
    float* sscale = red_q + 640;               // 80
    float* sshift = sscale + 80;               // 80
    float* scw    = sshift + 80;               // 80*20
    float* scb    = scw + 1600;                // 80
    float* h_s    = scb + 80;                  // 128*80

    const int tid  = threadIdx.x;
    const int w    = tid >> 5;
    const int lane = tid & 31;
    const int kq   = lane & 3;
    const int rq   = lane >> 2;
    const int mstrip = (w & 7) << 4;           // 8 m-strips of 16
    const int nbase  = (w >> 3) * 40;          // 2 n-halves of 40
    const int g0     = blockIdx.x * NTILE;

    // conv params (overlaps with pipeline prologue)
    for (int i = tid; i < NTILE * KER; i += 512)
        scw[i] = convw[(size_t)g0 * KER + i];
    if (tid < NTILE) scb[tid] = convb[g0 + tid];

    // ---- staging addresses (cp.async, 16B per thread) ----
    const int srow = tid >> 2;                 // 0..127
    const int sc   = (tid & 3) * 4;            // k sub-offset
    const float* zsrc = z + (size_t)srow * LATENT + sc;
    const float* wsrc = Wfc + (size_t)(g0 + srow) * LATENT + sc;  // valid only tid<320
    const bool   wact = (tid < 320);
    uint32_t stg_u32 = (uint32_t)__cvta_generic_to_shared(stg);
    const uint32_t zoff = (uint32_t)(srow * ZROW + sc) * 4u;
    const uint32_t woff = (uint32_t)(STAGE_Z + srow * ZROW + sc) * 4u;

    float d[5][4];
    #pragma unroll
    for (int i = 0; i < 5; ++i)
        #pragma unroll
        for (int j = 0; j < 4; ++j) d[i][j] = 0.f;

    // ---- prologue: fill stages 0..3 ----
    #pragma unroll
    for (int s = 0; s < STAGES - 1; ++s) {
        uint32_t base = stg_u32 + (uint32_t)(s * STAGE_F) * 4u;
        cp16(base + zoff, zsrc + s * KTILE);
        if (wact) cp16(base + woff, wsrc + s * KTILE);
        cp_commit();
    }

    // ---- main loop: 25 blocks of 5 tiles (static slot indices) ----
    for (int tb = 0; tb < 25; ++tb) {
        #pragma unroll
        for (int ti = 0; ti < STAGES; ++ti) {
            const int t = tb * STAGES + ti;
            asm volatile("cp.async.wait_group 3;\n");
            __syncthreads();
            const int tn = t + STAGES - 1;
            if (tn < KTILES) {
                uint32_t base = stg_u32 + (uint32_t)(((ti + STAGES - 1) % STAGES) * STAGE_F) * 4u;
                cp16(base + zoff, zsrc + tn * KTILE);
                if (wact) cp16(base + woff, wsrc + tn * KTILE);
            }
            cp_commit();

            const float* zb = stg + ti * STAGE_F;
            const float* wb = zb + STAGE_Z;
            #pragma unroll
            for (int ks = 0; ks < 2; ++ks) {
                const int kA = ks * 8 + kq;
                // raw f32 bits fed to tf32 mma (hardware truncation; ample rel_err headroom)
                const uint32_t a0 = __float_as_uint(zb[(mstrip + rq)     * ZROW + kA]);
                const uint32_t a1 = __float_as_uint(zb[(mstrip + rq + 8) * ZROW + kA]);
                const uint32_t a2 = __float_as_uint(zb[(mstrip + rq)     * ZROW + kA + 4]);
                const uint32_t a3 = __float_as_uint(zb[(mstrip + rq + 8) * ZROW + kA + 4]);
                #pragma unroll
                for (int nt = 0; nt < 5; ++nt) {
                    const uint32_t b0 = __float_as_uint(wb[(nbase + nt * 8 + rq) * ZROW + kA]);
                    const uint32_t b1 = __float_as_uint(wb[(nbase + nt * 8 + rq) * ZROW + kA + 4]);
                    asm volatile(
                        "mma.sync.aligned.m16n8k8.row.col.f32.tf32.tf32.f32 "
                        "{%0,%1,%2,%3}, {%4,%5,%6,%7}, {%8,%9}, {%0,%1,%2,%3};\n"
                        : "+f"(d[nt][0]), "+f"(d[nt][1]), "+f"(d[nt][2]), "+f"(d[nt][3])
                        : "r"(a0), "r"(a1), "r"(a2), "r"(a3), "r"(b0), "r"(b1));
                }
            }
        }
    }

    // ---- BatchNorm stats (b_fc cancels under mean subtraction) ----
    #pragma unroll
    for (int nt = 0; nt < 5; ++nt) {
        float s0 = d[nt][0] + d[nt][2];
        float s1 = d[nt][1] + d[nt][3];
        float q0 = d[nt][0] * d[nt][0] + d[nt][2] * d[nt][2];
        float q1 = d[nt][1] * d[nt][1] + d[nt][3] * d[nt][3];
        #pragma unroll
        for (int o = 4; o < 32; o <<= 1) {
            s0 += __shfl_xor_sync(0xffffffffu, s0, o);
            s1 += __shfl_xor_sync(0xffffffffu, s1, o);
            q0 += __shfl_xor_sync(0xffffffffu, q0, o);
            q1 += __shfl_xor_sync(0xffffffffu, q1, o);
        }
        if (rq == 0) {
            const int n = nbase + nt * 8 + kq * 2;
            red_s[(w & 7) * 80 + n]     = s0;
            red_s[(w & 7) * 80 + n + 1] = s1;
            red_q[(w & 7) * 80 + n]     = q0;
            red_q[(w & 7) * 80 + n + 1] = q1;
        }
    }
    __syncthreads();
    if (tid < NTILE) {
        float s = 0.f, q = 0.f;
        #pragma unroll
        for (int i = 0; i < 8; ++i) { s += red_s[i * 80 + tid]; q += red_q[i * 80 + tid]; }
        const float mean = s * (1.f / BATCH);
        const float var  = q * (1.f / BATCH) - mean * mean;
        const float scv  = gamma[g0 + tid] * rsqrtf(var + 1e-5f);
        sscale[tid] = scv;
        sshift[tid] = beta[g0 + tid] - mean * scv;
    }
    __syncthreads();

    // ---- normalize + LeakyReLU -> h_s ----
    #pragma unroll
    for (int nt = 0; nt < 5; ++nt) {
        #pragma unroll
        for (int c = 0; c < 4; ++c) {
            const int n = nbase + nt * 8 + kq * 2 + (c & 1);
            const int m = mstrip + rq + ((c >> 1) << 3);
            float hn = d[nt][c] * sscale[n] + sshift[n];
            hn = fmaxf(hn, 0.1f * hn);      // leaky relu
            h_s[m * 80 + n] = hn;
        }
    }
    __syncthreads();

    // ---- epilogue: outer-product conv + LeakyReLU + sigmoid, fully coalesced ----
    // per m-row: 80 groups * 20 taps = 1600 contiguous output floats = 400 float4
    const size_t outb = (size_t)g0 * KER;
    for (int i = tid; i < 128 * 400; i += 512) {
        const int m  = i / 400;
        const int j  = (i - m * 400) * 4;   // 0..1596 step 4 (within-n: 20 % 4 == 0)
        const int n  = j / 20;
        const int k  = j - n * 20;
        const float hn = h_s[m * 80 + n];
        const float cb = scb[n];
        const float4 wv = *(const float4*)&scw[n * KER + k];
        float4 y;
        float t0 = hn * wv.x + cb; t0 = fmaxf(t0, 0.1f * t0); y.x = sigf(t0);
        float t1 = hn * wv.y + cb; t1 = fmaxf(t1, 0.1f * t1); y.y = sigf(t1);
        float t2 = hn * wv.z + cb; t2 = fmaxf(t2, 0.1f * t2); y.z = sigf(t2);
        float t3 = hn * wv.w + cb; t3 = fmaxf(t3, 0.1f * t3); y.w = sigf(t3);
        *(float4*)(out + (size_t)m * ((size_t)NG * KER) + outb + j) = y;
    }
}

extern "C" void kernel_launch(void* const* d_in, const int* in_sizes, int n_in,
                              void* d_out, int out_size) {
    const float* z     = (const float*)d_in[0];
    const float* Wfc   = (const float*)d_in[1];
    // d_in[2] = b_fc: cancelled analytically by BN mean subtraction
    const float* gamma = (const float*)d_in[3];
    const float* beta  = (const float*)d_in[4];
    const float* convw = (const float*)d_in[5];
    const float* convb = (const float*)d_in[6];
    cudaFuncSetAttribute(fused_decoder, cudaFuncAttributeMaxDynamicSharedMemorySize, SMEM_BYTES);
    fused_decoder<<<NCTA, 512, SMEM_BYTES>>>(z, Wfc, gamma, beta, convw, convb, (float*)d_out);
}